// round 6
// baseline (speedup 1.0000x reference)
#include <cuda_runtime.h>
#include <cuda_bf16.h>
#include <cstdint>
#include <cstddef>

#define HIDDEN 2048
#define INTER  1408
#define TOKENS 4096
#define NEXP   8
#define MAX_MTILES 72
#define MAX_SLOTS  (MAX_MTILES * 128)

// ---------------- device scratch ----------------
__device__ __align__(16) __nv_bfloat16 g_Xhi[(size_t)MAX_SLOTS * HIDDEN];
__device__ __align__(16) __nv_bfloat16 g_Xlo[(size_t)MAX_SLOTS * HIDDEN];
__device__ __align__(16) __nv_bfloat16 g_Wg_hi[(size_t)NEXP * INTER * HIDDEN]; // [e][i][h]
__device__ __align__(16) __nv_bfloat16 g_Wg_lo[(size_t)NEXP * INTER * HIDDEN];
__device__ __align__(16) __nv_bfloat16 g_Wu_hi[(size_t)NEXP * INTER * HIDDEN];
__device__ __align__(16) __nv_bfloat16 g_Wu_lo[(size_t)NEXP * INTER * HIDDEN];
__device__ __align__(16) __nv_bfloat16 g_Wd_hi[(size_t)NEXP * HIDDEN * INTER]; // [e][h][i]
__device__ __align__(16) __nv_bfloat16 g_Wd_lo[(size_t)NEXP * HIDDEN * INTER];
__device__ __align__(16) __nv_bfloat16 g_Hhi[(size_t)MAX_SLOTS * INTER];
__device__ __align__(16) __nv_bfloat16 g_Hlo[(size_t)MAX_SLOTS * INTER];
__device__ __align__(16) float         g_G[(size_t)MAX_SLOTS * INTER];
__device__ __align__(16) float         g_U[(size_t)MAX_SLOTS * INTER];
__device__ __align__(16) float         g_Oslots[(size_t)MAX_SLOTS * HIDDEN];

__device__ int   g_top_idx[TOKENS * 2];
__device__ float g_top_w[TOKENS * 2];
__device__ int   g_counts[NEXP];
__device__ int   g_pos[NEXP];
__device__ int   g_expert_base[NEXP];
__device__ int   g_tile_expert[MAX_MTILES];
__device__ int   g_tile_slot0[MAX_MTILES];
__device__ int   g_perm_token[MAX_SLOTS];
__device__ int   g_token_slot[TOKENS * 2];

// ---------------- PTX helpers (baseline sm_80/sm_90 features only) ----------------
__device__ __forceinline__ uint32_t smem_u32(const void* p) {
    uint32_t a;
    asm("{ .reg .u64 t; cvta.to.shared.u64 t, %1; cvt.u32.u64 %0, t; }" : "=r"(a) : "l"(p));
    return a;
}
#define CP_ASYNC16(sa, gp) asm volatile("cp.async.cg.shared.global [%0], [%1], 16;" :: "r"(sa), "l"(gp))
#define CP_COMMIT()        asm volatile("cp.async.commit_group;" ::: "memory")
#define CP_WAIT0()         asm volatile("cp.async.wait_group 0;" ::: "memory")
#define CP_WAIT1()         asm volatile("cp.async.wait_group 1;" ::: "memory")

__device__ __forceinline__ void ldm_x4(uint32_t* r, uint32_t addr) {
    asm volatile("ldmatrix.sync.aligned.m8n8.x4.shared.b16 {%0,%1,%2,%3}, [%4];"
                 : "=r"(r[0]), "=r"(r[1]), "=r"(r[2]), "=r"(r[3]) : "r"(addr));
}
__device__ __forceinline__ void ldm_x2(uint32_t* r, uint32_t addr) {
    asm volatile("ldmatrix.sync.aligned.m8n8.x2.shared.b16 {%0,%1}, [%2];"
                 : "=r"(r[0]), "=r"(r[1]) : "r"(addr));
}
__device__ __forceinline__ void mma_bf16(float* c, const uint32_t* a, const uint32_t* b) {
    asm volatile("mma.sync.aligned.m16n8k16.row.col.f32.bf16.bf16.f32 "
                 "{%0,%1,%2,%3}, {%4,%5,%6,%7}, {%8,%9}, {%0,%1,%2,%3};"
                 : "+f"(c[0]), "+f"(c[1]), "+f"(c[2]), "+f"(c[3])
                 : "r"(a[0]), "r"(a[1]), "r"(a[2]), "r"(a[3]), "r"(b[0]), "r"(b[1]));
}
__device__ __forceinline__ uint32_t sw128(uint32_t off) { return off ^ ((off >> 3) & 0x70); }

// ---------------- aux kernels ----------------
__global__ void moe_init_kernel() {
    int i = blockIdx.x * blockDim.x + threadIdx.x;
    if (i < NEXP) { g_counts[i] = 0; g_pos[i] = 0; }
    if (i < MAX_SLOTS) g_perm_token[i] = -1;
}

__global__ void moe_router_kernel(const float* __restrict__ x, const float* __restrict__ rw) {
    int t = blockIdx.x;
    float acc[NEXP];
#pragma unroll
    for (int e = 0; e < NEXP; e++) acc[e] = 0.f;
    for (int c = threadIdx.x; c < HIDDEN; c += 256) {
        float xv = x[(size_t)t * HIDDEN + c];
#pragma unroll
        for (int e = 0; e < NEXP; e++) acc[e] += xv * rw[e * HIDDEN + c];
    }
#pragma unroll
    for (int o = 16; o > 0; o >>= 1)
#pragma unroll
        for (int e = 0; e < NEXP; e++) acc[e] += __shfl_down_sync(0xFFFFFFFFu, acc[e], o);
    __shared__ float red[8][NEXP];
    int wid = threadIdx.x >> 5, lid = threadIdx.x & 31;
    if (lid == 0)
#pragma unroll
        for (int e = 0; e < NEXP; e++) red[wid][e] = acc[e];
    __syncthreads();
    if (threadIdx.x == 0) {
        float l[NEXP];
#pragma unroll
        for (int e = 0; e < NEXP; e++) {
            float s = 0.f;
            for (int w = 0; w < 8; w++) s += red[w][e];
            l[e] = s;
        }
        int i0 = 0;
        for (int e = 1; e < NEXP; e++) if (l[e] > l[i0]) i0 = e;
        int i1 = (i0 == 0) ? 1 : 0;
        for (int e = 0; e < NEXP; e++) if (e != i0 && l[e] > l[i1]) i1 = e;
        float e1 = __expf(l[i1] - l[i0]);
        float inv = 1.f / (1.f + e1);
        g_top_idx[t * 2 + 0] = i0;  g_top_w[t * 2 + 0] = inv;
        g_top_idx[t * 2 + 1] = i1;  g_top_w[t * 2 + 1] = e1 * inv;
        atomicAdd(&g_counts[i0], 1);
        atomicAdd(&g_counts[i1], 1);
    }
}

__global__ void moe_schedule_kernel() {
    int base = 0, mt = 0;
    for (int e = 0; e < NEXP; e++) {
        g_expert_base[e] = base;
        int nt = (g_counts[e] + 127) >> 7;
        for (int i = 0; i < nt; i++) { g_tile_expert[mt] = e; g_tile_slot0[mt] = base + i * 128; mt++; }
        base += nt * 128;
    }
    for (; mt < MAX_MTILES; mt++) g_tile_expert[mt] = -1;
}

__global__ void moe_assign_kernel() {
    int t = blockIdx.x * blockDim.x + threadIdx.x;
    if (t >= TOKENS) return;
#pragma unroll
    for (int k = 0; k < 2; k++) {
        int e = g_top_idx[t * 2 + k];
        int p = atomicAdd(&g_pos[e], 1);
        int s = g_expert_base[e] + p;
        g_perm_token[s] = t;
        g_token_slot[t * 2 + k] = s;
    }
}

union U8 { ushort u[8]; uint4 q; };

__global__ void moe_gather_kernel(const float* __restrict__ x) {
    int s = blockIdx.x;
    int t = g_perm_token[s];
    int c = threadIdx.x * 8;
    float v[8];
    if (t >= 0) {
        const float4* xp = reinterpret_cast<const float4*>(x + (size_t)t * HIDDEN + c);
        float4 a = xp[0], b = xp[1];
        v[0]=a.x; v[1]=a.y; v[2]=a.z; v[3]=a.w; v[4]=b.x; v[5]=b.y; v[6]=b.z; v[7]=b.w;
    } else {
#pragma unroll
        for (int i = 0; i < 8; i++) v[i] = 0.f;
    }
    U8 hi, lo;
#pragma unroll
    for (int i = 0; i < 8; i++) {
        __nv_bfloat16 h = __float2bfloat16(v[i]);
        float r = v[i] - __bfloat162float(h);
        hi.u[i] = __bfloat16_as_ushort(h);
        lo.u[i] = __bfloat16_as_ushort(__float2bfloat16(r));
    }
    *reinterpret_cast<uint4*>(g_Xhi + (size_t)s * HIDDEN + c) = hi.q;
    *reinterpret_cast<uint4*>(g_Xlo + (size_t)s * HIDDEN + c) = lo.q;
}

// Transpose [R,C] -> [C,R] per expert with bf16 hi/lo split. block (32,8).
__global__ void moe_transpose_kernel(const float* __restrict__ src, int R, int C, int which) {
    __shared__ float tile[32][33];
    int e = blockIdx.z;
    const float* s = src + (size_t)e * R * C;
    size_t doff = (size_t)e * R * C;
    __nv_bfloat16 *dh, *dl;
    if (which == 0)      { dh = g_Wg_hi + doff; dl = g_Wg_lo + doff; }
    else if (which == 1) { dh = g_Wu_hi + doff; dl = g_Wu_lo + doff; }
    else                 { dh = g_Wd_hi + doff; dl = g_Wd_lo + doff; }
    int c0 = blockIdx.x * 32, r0 = blockIdx.y * 32;
    int tx = threadIdx.x, ty = threadIdx.y;
#pragma unroll
    for (int j = 0; j < 4; j++)
        tile[ty + 8 * j][tx] = s[(size_t)(r0 + ty + 8 * j) * C + c0 + tx];
    __syncthreads();
#pragma unroll
    for (int j = 0; j < 4; j++) {
        float v = tile[tx][ty + 8 * j];
        int oc = c0 + ty + 8 * j, orr = r0 + tx;
        __nv_bfloat16 h = __float2bfloat16(v);
        float r = v - __bfloat162float(h);
        dh[(size_t)oc * R + orr] = h;
        dl[(size_t)oc * R + orr] = __float2bfloat16(r);
    }
}

// ---------------- HMMA GEMM: C[128x128] = A[128xK] * B[128 rows x K]^T, split-bf16 ----------------
// smem stage: Ah(16K) Al(16K) Bh(16K) Bl(16K) = 64KB; 2 stages = 128KB.
#define STAGE_BYTES 65536
#define GEMM_SMEM   (2 * STAGE_BYTES)

__device__ __forceinline__ void load_plane(const __nv_bfloat16* __restrict__ src, int ldk,
                                           uint32_t plane, int tid) {
#pragma unroll
    for (int it = 0; it < 4; it++) {
        int idx = tid + it * 256;
        int row = idx >> 3, v = idx & 7;
        const __nv_bfloat16* g = src + (size_t)row * ldk + v * 8;
        CP_ASYNC16(plane + sw128((uint32_t)(row * 128 + v * 16)), g);
    }
}

__device__ __forceinline__ void gemm_body(const __nv_bfloat16* Ah, const __nv_bfloat16* Al,
                                          const __nv_bfloat16* Bh, const __nv_bfloat16* Bl,
                                          float* Crow, int K, int Ntot, int slot0, int n0,
                                          char* smem, int tid) {
    uint32_t sb = smem_u32(smem);
    int wid = tid >> 5, lane = tid & 31;
    int wm = wid & 1, wn = wid >> 1;           // 2 x 4 warps, warp tile 64 x 32

    float acc[4][4][4];
#pragma unroll
    for (int i = 0; i < 4; i++)
#pragma unroll
        for (int j = 0; j < 4; j++)
#pragma unroll
            for (int c = 0; c < 4; c++) acc[i][j][c] = 0.f;

    const int NK = K / 64;
    // prologue
    {
        uint32_t base = sb;
        load_plane(Ah, K, base,          tid);
        load_plane(Al, K, base + 16384,  tid);
        load_plane(Bh, K, base + 32768,  tid);
        load_plane(Bl, K, base + 49152,  tid);
        CP_COMMIT();
    }
    // precomputed intra-warp ldmatrix offsets (within a plane)
    uint32_t a_off[4], b_off[4];
#pragma unroll
    for (int mt = 0; mt < 4; mt++) {
        int row = wm * 64 + mt * 16 + (lane & 15);
        a_off[mt] = sw128((uint32_t)(row * 128 + (lane >> 4) * 16));
    }
#pragma unroll
    for (int nt = 0; nt < 4; nt++) {
        int row = wn * 32 + nt * 8 + (lane & 7);
        b_off[nt] = sw128((uint32_t)(row * 128 + ((lane >> 3) & 1) * 16));
    }

    for (int kc = 0; kc < NK; kc++) {
        uint32_t cur = sb + (uint32_t)(kc & 1) * STAGE_BYTES;
        if (kc + 1 < NK) {
            uint32_t nxt = sb + (uint32_t)((kc + 1) & 1) * STAGE_BYTES;
            int k0 = (kc + 1) * 64;
            load_plane(Ah + k0, K, nxt,          tid);
            load_plane(Al + k0, K, nxt + 16384,  tid);
            load_plane(Bh + k0, K, nxt + 32768,  tid);
            load_plane(Bl + k0, K, nxt + 49152,  tid);
            CP_COMMIT();
            CP_WAIT1();
        } else {
            CP_WAIT0();
        }
        __syncthreads();
#pragma unroll
        for (int s = 0; s < 4; s++) {
            uint32_t ks = (uint32_t)(s * 32);
            uint32_t ahf[4][4], alf[4][4];
#pragma unroll
            for (int mt = 0; mt < 4; mt++) {
                ldm_x4(ahf[mt], cur + (a_off[mt] ^ ks));
                ldm_x4(alf[mt], cur + 16384 + (a_off[mt] ^ ks));
            }
#pragma unroll
            for (int nt = 0; nt < 4; nt++) {
                uint32_t bhf[2], blf[2];
                ldm_x2(bhf, cur + 32768 + (b_off[nt] ^ ks));
                ldm_x2(blf, cur + 49152 + (b_off[nt] ^ ks));
#pragma unroll
                for (int mt = 0; mt < 4; mt++) {
                    mma_bf16(acc[mt][nt], ahf[mt], bhf);
                    mma_bf16(acc[mt][nt], alf[mt], bhf);
                    mma_bf16(acc[mt][nt], ahf[mt], blf);
                }
            }
        }
        __syncthreads();
    }
    // epilogue: fp32 store
    int r_base = wm * 64 + (lane >> 2);
    int c_base = n0 + wn * 32 + (lane & 3) * 2;
#pragma unroll
    for (int mt = 0; mt < 4; mt++) {
#pragma unroll
        for (int nt = 0; nt < 4; nt++) {
            int r = r_base + mt * 16;
            int c = c_base + nt * 8;
            float* p0 = Crow + (size_t)r * Ntot + c;
            float* p1 = Crow + (size_t)(r + 8) * Ntot + c;
            *reinterpret_cast<float2*>(p0) = make_float2(acc[mt][nt][0], acc[mt][nt][1]);
            *reinterpret_cast<float2*>(p1) = make_float2(acc[mt][nt][2], acc[mt][nt][3]);
        }
    }
}

// GEMM1: z=0 gate -> g_G, z=1 up -> g_U.  A = X tiles, B = Wg/Wu, K=HIDDEN, Ntot=INTER
__global__ __launch_bounds__(256) void moe_gemm1() {
    extern __shared__ char smem[];
    int e = g_tile_expert[blockIdx.x];
    if (e < 0) return;
    int slot0 = g_tile_slot0[blockIdx.x];
    int n0 = blockIdx.y * 128;
    const __nv_bfloat16 *Bh, *Bl;
    float* C;
    size_t boff = ((size_t)e * INTER + n0) * HIDDEN;
    if (blockIdx.z == 0) { Bh = g_Wg_hi + boff; Bl = g_Wg_lo + boff; C = g_G; }
    else                 { Bh = g_Wu_hi + boff; Bl = g_Wu_lo + boff; C = g_U; }
    gemm_body(g_Xhi + (size_t)slot0 * HIDDEN, g_Xlo + (size_t)slot0 * HIDDEN,
              Bh, Bl, C + (size_t)slot0 * INTER, HIDDEN, INTER, slot0, n0,
              smem, threadIdx.x);
}

// SiLU + split: H = silu(G)*U -> bf16 hi/lo
__global__ void moe_silu_kernel() {
    int s = blockIdx.x;
    const float4* gp = reinterpret_cast<const float4*>(g_G + (size_t)s * INTER);
    const float4* up = reinterpret_cast<const float4*>(g_U + (size_t)s * INTER);
    for (int idx = threadIdx.x; idx < INTER / 4; idx += 256) {
        float4 g = gp[idx], u = up[idx];
        float h[4];
        h[0] = g.x / (1.f + __expf(-g.x)) * u.x;
        h[1] = g.y / (1.f + __expf(-g.y)) * u.y;
        h[2] = g.z / (1.f + __expf(-g.z)) * u.z;
        h[3] = g.w / (1.f + __expf(-g.w)) * u.w;
        ushort hh[4], hl[4];
#pragma unroll
        for (int i = 0; i < 4; i++) {
            __nv_bfloat16 b = __float2bfloat16(h[i]);
            float r = h[i] - __bfloat162float(b);
            hh[i] = __bfloat16_as_ushort(b);
            hl[i] = __bfloat16_as_ushort(__float2bfloat16(r));
        }
        *reinterpret_cast<uint2*>(g_Hhi + (size_t)s * INTER + idx * 4) = *reinterpret_cast<uint2*>(hh);
        *reinterpret_cast<uint2*>(g_Hlo + (size_t)s * INTER + idx * 4) = *reinterpret_cast<uint2*>(hl);
    }
}

// GEMM2: down.  A = H tiles, B = Wd, K=INTER, Ntot=HIDDEN
__global__ __launch_bounds__(256) void moe_gemm2() {
    extern __shared__ char smem[];
    int e = g_tile_expert[blockIdx.x];
    if (e < 0) return;
    int slot0 = g_tile_slot0[blockIdx.x];
    int n0 = blockIdx.y * 128;
    size_t boff = ((size_t)e * HIDDEN + n0) * INTER;
    gemm_body(g_Hhi + (size_t)slot0 * INTER, g_Hlo + (size_t)slot0 * INTER,
              g_Wd_hi + boff, g_Wd_lo + boff,
              g_Oslots + (size_t)slot0 * HIDDEN, INTER, HIDDEN, slot0, n0,
              smem, threadIdx.x);
}

__global__ void moe_combine_kernel(float* __restrict__ out) {
    int t = blockIdx.x;
    int c = threadIdx.x * 8;
    int s0 = g_token_slot[t * 2], s1 = g_token_slot[t * 2 + 1];
    float w0 = g_top_w[t * 2], w1 = g_top_w[t * 2 + 1];
    const float4* a = reinterpret_cast<const float4*>(g_Oslots + (size_t)s0 * HIDDEN + c);
    const float4* b = reinterpret_cast<const float4*>(g_Oslots + (size_t)s1 * HIDDEN + c);
    float4* o = reinterpret_cast<float4*>(out + (size_t)t * HIDDEN + c);
#pragma unroll
    for (int j = 0; j < 2; j++) {
        float4 av = a[j], bv = b[j];
        o[j] = make_float4(w0 * av.x + w1 * bv.x, w0 * av.y + w1 * bv.y,
                           w0 * av.z + w1 * bv.z, w0 * av.w + w1 * bv.w);
    }
}

// ---------------- launch ----------------
extern "C" void kernel_launch(void* const* d_in, const int* in_sizes, int n_in,
                              void* d_out, int out_size) {
    const float* x  = (const float*)d_in[0];
    const float* rw = (const float*)d_in[1];
    const float* wg = (const float*)d_in[2];
    const float* wu = (const float*)d_in[3];
    const float* wd = (const float*)d_in[4];
    float* out = (float*)d_out;

    cudaFuncSetAttribute(moe_gemm1, cudaFuncAttributeMaxDynamicSharedMemorySize, GEMM_SMEM);
    cudaFuncSetAttribute(moe_gemm2, cudaFuncAttributeMaxDynamicSharedMemorySize, GEMM_SMEM);

    dim3 tb(32, 8);
    moe_init_kernel<<<(MAX_SLOTS + 255) / 256, 256>>>();
    moe_transpose_kernel<<<dim3(INTER / 32, HIDDEN / 32, NEXP), tb>>>(wg, HIDDEN, INTER, 0);
    moe_transpose_kernel<<<dim3(INTER / 32, HIDDEN / 32, NEXP), tb>>>(wu, HIDDEN, INTER, 1);
    moe_transpose_kernel<<<dim3(HIDDEN / 32, INTER / 32, NEXP), tb>>>(wd, INTER, HIDDEN, 2);
    moe_router_kernel<<<TOKENS, 256>>>(x, rw);
    moe_schedule_kernel<<<1, 1>>>();
    moe_assign_kernel<<<(TOKENS + 255) / 256, 256>>>();
    moe_gather_kernel<<<MAX_SLOTS, 256>>>(x);
    moe_gemm1<<<dim3(MAX_MTILES, INTER / 128, 2), 256, GEMM_SMEM>>>();
    moe_silu_kernel<<<MAX_SLOTS, 256>>>();
    moe_gemm2<<<dim3(MAX_MTILES, HIDDEN / 128), 256, GEMM_SMEM>>>();
    moe_combine_kernel<<<TOKENS, 256>>>(out);
}

// round 8
// speedup vs baseline: 2.3930x; 2.3930x over previous
#include <cuda_runtime.h>
#include <cuda_fp16.h>
#include <cstdint>
#include <cstddef>

#define HIDDEN 2048
#define INTER  1408
#define TOKENS 4096
#define NEXP   8
#define MAX_MTILES 72
#define MAX_SLOTS  (MAX_MTILES * 128)

// ---------------- device scratch ----------------
__device__ __align__(16) __half g_Xhi[(size_t)MAX_SLOTS * HIDDEN];
__device__ __align__(16) __half g_Xlo[(size_t)MAX_SLOTS * HIDDEN];
__device__ __align__(16) __half g_Wg[(size_t)NEXP * INTER * HIDDEN]; // [e][i][h]
__device__ __align__(16) __half g_Wu[(size_t)NEXP * INTER * HIDDEN];
__device__ __align__(16) __half g_Wd[(size_t)NEXP * HIDDEN * INTER]; // [e][h][i]
__device__ __align__(16) __half g_Hhi[(size_t)MAX_SLOTS * INTER];
__device__ __align__(16) __half g_Hlo[(size_t)MAX_SLOTS * INTER];
__device__ __align__(16) float  g_Oslots[(size_t)MAX_SLOTS * HIDDEN];

__device__ int   g_top_idx[TOKENS * 2];
__device__ float g_top_w[TOKENS * 2];
__device__ int   g_counts[NEXP];
__device__ int   g_pos[NEXP];
__device__ int   g_expert_base[NEXP];
__device__ int   g_tile_expert[MAX_MTILES];
__device__ int   g_tile_slot0[MAX_MTILES];
__device__ int   g_perm_token[MAX_SLOTS];
__device__ int   g_token_slot[TOKENS * 2];

// ---------------- PTX helpers ----------------
__device__ __forceinline__ uint32_t smem_u32(const void* p) {
    uint32_t a;
    asm("{ .reg .u64 t; cvta.to.shared.u64 t, %1; cvt.u32.u64 %0, t; }" : "=r"(a) : "l"(p));
    return a;
}
#define CP_ASYNC16(sa, gp) asm volatile("cp.async.cg.shared.global [%0], [%1], 16;" :: "r"(sa), "l"(gp))
#define CP_COMMIT()        asm volatile("cp.async.commit_group;" ::: "memory")
#define CP_WAIT0()         asm volatile("cp.async.wait_group 0;" ::: "memory")
#define CP_WAIT1()         asm volatile("cp.async.wait_group 1;" ::: "memory")

__device__ __forceinline__ void ldm_x4(uint32_t* r, uint32_t addr) {
    asm volatile("ldmatrix.sync.aligned.m8n8.x4.shared.b16 {%0,%1,%2,%3}, [%4];"
                 : "=r"(r[0]), "=r"(r[1]), "=r"(r[2]), "=r"(r[3]) : "r"(addr));
}
__device__ __forceinline__ void ldm_x2(uint32_t* r, uint32_t addr) {
    asm volatile("ldmatrix.sync.aligned.m8n8.x2.shared.b16 {%0,%1}, [%2];"
                 : "=r"(r[0]), "=r"(r[1]) : "r"(addr));
}
__device__ __forceinline__ void mma_f16(float* c, const uint32_t* a, const uint32_t* b) {
    asm volatile("mma.sync.aligned.m16n8k16.row.col.f32.f16.f16.f32 "
                 "{%0,%1,%2,%3}, {%4,%5,%6,%7}, {%8,%9}, {%0,%1,%2,%3};"
                 : "+f"(c[0]), "+f"(c[1]), "+f"(c[2]), "+f"(c[3])
                 : "r"(a[0]), "r"(a[1]), "r"(a[2]), "r"(a[3]), "r"(b[0]), "r"(b[1]));
}
__device__ __forceinline__ uint32_t sw128(uint32_t off) { return off ^ ((off >> 3) & 0x70); }

// ---------------- aux kernels ----------------
__global__ void moe_init_kernel() {
    int i = blockIdx.x * blockDim.x + threadIdx.x;
    if (i < NEXP) { g_counts[i] = 0; g_pos[i] = 0; }
    if (i < MAX_SLOTS) g_perm_token[i] = -1;
}

__global__ void moe_router_kernel(const float* __restrict__ x, const float* __restrict__ rw) {
    int t = blockIdx.x;
    float acc[NEXP];
#pragma unroll
    for (int e = 0; e < NEXP; e++) acc[e] = 0.f;
    for (int c = threadIdx.x; c < HIDDEN; c += 256) {
        float xv = x[(size_t)t * HIDDEN + c];
#pragma unroll
        for (int e = 0; e < NEXP; e++) acc[e] += xv * rw[e * HIDDEN + c];
    }
#pragma unroll
    for (int o = 16; o > 0; o >>= 1)
#pragma unroll
        for (int e = 0; e < NEXP; e++) acc[e] += __shfl_down_sync(0xFFFFFFFFu, acc[e], o);
    __shared__ float red[8][NEXP];
    int wid = threadIdx.x >> 5, lid = threadIdx.x & 31;
    if (lid == 0)
#pragma unroll
        for (int e = 0; e < NEXP; e++) red[wid][e] = acc[e];
    __syncthreads();
    if (threadIdx.x == 0) {
        float l[NEXP];
#pragma unroll
        for (int e = 0; e < NEXP; e++) {
            float s = 0.f;
            for (int w = 0; w < 8; w++) s += red[w][e];
            l[e] = s;
        }
        int i0 = 0;
        for (int e = 1; e < NEXP; e++) if (l[e] > l[i0]) i0 = e;
        int i1 = (i0 == 0) ? 1 : 0;
        for (int e = 0; e < NEXP; e++) if (e != i0 && l[e] > l[i1]) i1 = e;
        float e1 = __expf(l[i1] - l[i0]);
        float inv = 1.f / (1.f + e1);
        g_top_idx[t * 2 + 0] = i0;  g_top_w[t * 2 + 0] = inv;
        g_top_idx[t * 2 + 1] = i1;  g_top_w[t * 2 + 1] = e1 * inv;
        atomicAdd(&g_counts[i0], 1);
        atomicAdd(&g_counts[i1], 1);
    }
}

__global__ void moe_schedule_kernel() {
    int base = 0, mt = 0;
    for (int e = 0; e < NEXP; e++) {
        g_expert_base[e] = base;
        int nt = (g_counts[e] + 127) >> 7;
        for (int i = 0; i < nt && mt < MAX_MTILES; i++) {
            g_tile_expert[mt] = e;
            g_tile_slot0[mt] = base + i * 128;
            mt++;
        }
        base += nt * 128;
    }
    for (; mt < MAX_MTILES; mt++) g_tile_expert[mt] = -1;
}

__global__ void moe_assign_kernel() {
    int t = blockIdx.x * blockDim.x + threadIdx.x;
    if (t >= TOKENS) return;
#pragma unroll
    for (int k = 0; k < 2; k++) {
        int e = g_top_idx[t * 2 + k];
        int p = atomicAdd(&g_pos[e], 1);
        int s = g_expert_base[e] + p;
        g_perm_token[s] = t;
        g_token_slot[t * 2 + k] = s;
    }
}

union U8 { ushort u[8]; uint4 q; };

__global__ void moe_gather_kernel(const float* __restrict__ x) {
    int s = blockIdx.x;
    int t = g_perm_token[s];
    int c = threadIdx.x * 8;
    float v[8];
    if (t >= 0) {
        const float4* xp = reinterpret_cast<const float4*>(x + (size_t)t * HIDDEN + c);
        float4 a = xp[0], b = xp[1];
        v[0]=a.x; v[1]=a.y; v[2]=a.z; v[3]=a.w; v[4]=b.x; v[5]=b.y; v[6]=b.z; v[7]=b.w;
    } else {
#pragma unroll
        for (int i = 0; i < 8; i++) v[i] = 0.f;
    }
    U8 hi, lo;
#pragma unroll
    for (int i = 0; i < 8; i++) {
        __half h = __float2half_rn(v[i]);
        float r = v[i] - __half2float(h);
        hi.u[i] = __half_as_ushort(h);
        lo.u[i] = __half_as_ushort(__float2half_rn(r));
    }
    *reinterpret_cast<uint4*>(g_Xhi + (size_t)s * HIDDEN + c) = hi.q;
    *reinterpret_cast<uint4*>(g_Xlo + (size_t)s * HIDDEN + c) = lo.q;
}

// Transpose [R,C] -> [C,R] per expert, fp16 out. block (32,8).
__global__ void moe_transpose_kernel(const float* __restrict__ src, int R, int C, int which) {
    __shared__ float tile[32][33];
    int e = blockIdx.z;
    const float* s = src + (size_t)e * R * C;
    size_t doff = (size_t)e * R * C;
    __half* dh;
    if (which == 0)      dh = g_Wg + doff;
    else if (which == 1) dh = g_Wu + doff;
    else                 dh = g_Wd + doff;
    int c0 = blockIdx.x * 32, r0 = blockIdx.y * 32;
    int tx = threadIdx.x, ty = threadIdx.y;
#pragma unroll
    for (int j = 0; j < 4; j++)
        tile[ty + 8 * j][tx] = s[(size_t)(r0 + ty + 8 * j) * C + c0 + tx];
    __syncthreads();
#pragma unroll
    for (int j = 0; j < 4; j++) {
        float v = tile[tx][ty + 8 * j];
        int oc = c0 + ty + 8 * j, orr = r0 + tx;
        dh[(size_t)oc * R + orr] = __float2half_rn(v);
    }
}

// ---------------- smem loaders ----------------
// 128 rows x 64 halfs (128B rows) -> SW128 smem, cp.async; 256 threads
__device__ __forceinline__ void load_plane128(const __half* __restrict__ src, int ldk,
                                              uint32_t plane, int tid) {
#pragma unroll
    for (int it = 0; it < 4; it++) {
        int idx = tid + it * 256;
        int row = idx >> 3, v = idx & 7;
        CP_ASYNC16(plane + sw128((uint32_t)(row * 128 + v * 16)), src + (size_t)row * ldk + v * 8);
    }
}
// 64 rows x 64 halfs
__device__ __forceinline__ void load_plane64(const __half* __restrict__ src, int ldk,
                                             uint32_t plane, int tid) {
#pragma unroll
    for (int it = 0; it < 2; it++) {
        int idx = tid + it * 256;
        int row = idx >> 3, v = idx & 7;
        CP_ASYNC16(plane + sw128((uint32_t)(row * 128 + v * 16)), src + (size_t)row * ldk + v * 8);
    }
}

__device__ __forceinline__ float silu_mul(float g, float u) {
    return g / (1.f + __expf(-g)) * u;
}

// ---------------- GEMM1: fused gate+up+SiLU.  A[128xK] (hi+lo), Bg/Bu[64xK].  K=HIDDEN ----------------
// stage: Ah 16K | Al 16K | Bg 8K | Bu 8K = 48KB; 2 stages = 96KB
#define G1_STAGE 49152
#define G1_SMEM  (2 * G1_STAGE)
__global__ __launch_bounds__(256, 2) void moe_gemm1() {
    extern __shared__ char smem[];
    uint32_t sb = smem_u32(smem);
    int e = g_tile_expert[blockIdx.x];
    if (e < 0) return;
    int slot0 = g_tile_slot0[blockIdx.x];
    int n0 = blockIdx.y * 64;
    int tid = threadIdx.x, wid = tid >> 5, lane = tid & 31;
    int wm = wid & 1, wn = wid >> 1;   // warp tile: 64 rows x 16 cols (per matrix)

    const __half* Ah = g_Xhi + (size_t)slot0 * HIDDEN;
    const __half* Al = g_Xlo + (size_t)slot0 * HIDDEN;
    const __half* Bg = g_Wg + ((size_t)e * INTER + n0) * HIDDEN;
    const __half* Bu = g_Wu + ((size_t)e * INTER + n0) * HIDDEN;

    float ag[4][2][4], au[4][2][4];
#pragma unroll
    for (int i = 0; i < 4; i++)
#pragma unroll
        for (int j = 0; j < 2; j++)
#pragma unroll
            for (int c = 0; c < 4; c++) { ag[i][j][c] = 0.f; au[i][j][c] = 0.f; }

    const int NK = HIDDEN / 64;
    load_plane128(Ah, HIDDEN, sb,          tid);
    load_plane128(Al, HIDDEN, sb + 16384,  tid);
    load_plane64 (Bg, HIDDEN, sb + 32768,  tid);
    load_plane64 (Bu, HIDDEN, sb + 40960,  tid);
    CP_COMMIT();

    uint32_t a_off[4], b_off[2];
#pragma unroll
    for (int mt = 0; mt < 4; mt++) {
        int row = wm * 64 + mt * 16 + (lane & 15);
        a_off[mt] = sw128((uint32_t)(row * 128 + (lane >> 4) * 16));
    }
#pragma unroll
    for (int nt = 0; nt < 2; nt++) {
        int row = wn * 16 + nt * 8 + (lane & 7);
        b_off[nt] = sw128((uint32_t)(row * 128 + ((lane >> 3) & 1) * 16));
    }

    for (int kc = 0; kc < NK; kc++) {
        uint32_t cur = sb + (uint32_t)(kc & 1) * G1_STAGE;
        if (kc + 1 < NK) {
            uint32_t nxt = sb + (uint32_t)((kc + 1) & 1) * G1_STAGE;
            int k0 = (kc + 1) * 64;
            load_plane128(Ah + k0, HIDDEN, nxt,          tid);
            load_plane128(Al + k0, HIDDEN, nxt + 16384,  tid);
            load_plane64 (Bg + k0, HIDDEN, nxt + 32768,  tid);
            load_plane64 (Bu + k0, HIDDEN, nxt + 40960,  tid);
            CP_COMMIT();
            CP_WAIT1();
        } else {
            CP_WAIT0();
        }
        __syncthreads();
#pragma unroll
        for (int s = 0; s < 4; s++) {
            uint32_t ks = (uint32_t)(s * 32);
            uint32_t ahf[4][4], alf[4][4];
#pragma unroll
            for (int mt = 0; mt < 4; mt++) {
                ldm_x4(ahf[mt], cur + (a_off[mt] ^ ks));
                ldm_x4(alf[mt], cur + 16384 + (a_off[mt] ^ ks));
            }
#pragma unroll
            for (int nt = 0; nt < 2; nt++) {
                uint32_t bg[2], bu[2];
                ldm_x2(bg, cur + 32768 + (b_off[nt] ^ ks));
                ldm_x2(bu, cur + 40960 + (b_off[nt] ^ ks));
#pragma unroll
                for (int mt = 0; mt < 4; mt++) {
                    mma_f16(ag[mt][nt], ahf[mt], bg);
                    mma_f16(ag[mt][nt], alf[mt], bg);
                    mma_f16(au[mt][nt], ahf[mt], bu);
                    mma_f16(au[mt][nt], alf[mt], bu);
                }
            }
        }
        __syncthreads();
    }
    // SiLU epilogue -> H hi/lo (fp16)
    int r_base = wm * 64 + (lane >> 2);
    int c_base = n0 + wn * 16 + (lane & 3) * 2;
#pragma unroll
    for (int mt = 0; mt < 4; mt++) {
#pragma unroll
        for (int nt = 0; nt < 2; nt++) {
            int c = c_base + nt * 8;
#pragma unroll
            for (int half_ = 0; half_ < 2; half_++) {
                int r = r_base + mt * 16 + half_ * 8;
                float h0 = silu_mul(ag[mt][nt][half_ * 2],     au[mt][nt][half_ * 2]);
                float h1 = silu_mul(ag[mt][nt][half_ * 2 + 1], au[mt][nt][half_ * 2 + 1]);
                __half b0 = __float2half_rn(h0), b1 = __float2half_rn(h1);
                float r0 = h0 - __half2float(b0), r1 = h1 - __half2float(b1);
                size_t off = (size_t)(slot0 + r) * INTER + c;
                *reinterpret_cast<__half2*>(g_Hhi + off) = __halves2half2(b0, b1);
                *reinterpret_cast<__half2*>(g_Hlo + off) =
                    __halves2half2(__float2half_rn(r0), __float2half_rn(r1));
            }
        }
    }
}

// ---------------- GEMM2: down.  A = H (hi+lo), B = Wd[128xK]. K=INTER ----------------
// stage: Ah 16K | Al 16K | B 16K = 48KB; 2 stages = 96KB
#define G2_STAGE 49152
#define G2_SMEM  (2 * G2_STAGE)
__global__ __launch_bounds__(256, 2) void moe_gemm2() {
    extern __shared__ char smem[];
    uint32_t sb = smem_u32(smem);
    int e = g_tile_expert[blockIdx.x];
    if (e < 0) return;
    int slot0 = g_tile_slot0[blockIdx.x];
    int n0 = blockIdx.y * 128;
    int tid = threadIdx.x, wid = tid >> 5, lane = tid & 31;
    int wm = wid & 1, wn = wid >> 1;   // warp tile 64 x 32

    const __half* Ah = g_Hhi + (size_t)slot0 * INTER;
    const __half* Al = g_Hlo + (size_t)slot0 * INTER;
    const __half* B  = g_Wd + ((size_t)e * HIDDEN + n0) * INTER;

    float acc[4][4][4];
#pragma unroll
    for (int i = 0; i < 4; i++)
#pragma unroll
        for (int j = 0; j < 4; j++)
#pragma unroll
            for (int c = 0; c < 4; c++) acc[i][j][c] = 0.f;

    const int NK = INTER / 64;
    load_plane128(Ah, INTER, sb,          tid);
    load_plane128(Al, INTER, sb + 16384,  tid);
    load_plane128(B,  INTER, sb + 32768,  tid);
    CP_COMMIT();

    uint32_t a_off[4], b_off[4];
#pragma unroll
    for (int mt = 0; mt < 4; mt++) {
        int row = wm * 64 + mt * 16 + (lane & 15);
        a_off[mt] = sw128((uint32_t)(row * 128 + (lane >> 4) * 16));
    }
#pragma unroll
    for (int nt = 0; nt < 4; nt++) {
        int row = wn * 32 + nt * 8 + (lane & 7);
        b_off[nt] = sw128((uint32_t)(row * 128 + ((lane >> 3) & 1) * 16));
    }

    for (int kc = 0; kc < NK; kc++) {
        uint32_t cur = sb + (uint32_t)(kc & 1) * G2_STAGE;
        if (kc + 1 < NK) {
            uint32_t nxt = sb + (uint32_t)((kc + 1) & 1) * G2_STAGE;
            int k0 = (kc + 1) * 64;
            load_plane128(Ah + k0, INTER, nxt,          tid);
            load_plane128(Al + k0, INTER, nxt + 16384,  tid);
            load_plane128(B  + k0, INTER, nxt + 32768,  tid);
            CP_COMMIT();
            CP_WAIT1();
        } else {
            CP_WAIT0();
        }
        __syncthreads();
#pragma unroll
        for (int s = 0; s < 4; s++) {
            uint32_t ks = (uint32_t)(s * 32);
            uint32_t ahf[4][4], alf[4][4];
#pragma unroll
            for (int mt = 0; mt < 4; mt++) {
                ldm_x4(ahf[mt], cur + (a_off[mt] ^ ks));
                ldm_x4(alf[mt], cur + 16384 + (a_off[mt] ^ ks));
            }
#pragma unroll
            for (int nt = 0; nt < 4; nt++) {
                uint32_t bf[2];
                ldm_x2(bf, cur + 32768 + (b_off[nt] ^ ks));
#pragma unroll
                for (int mt = 0; mt < 4; mt++) {
                    mma_f16(acc[mt][nt], ahf[mt], bf);
                    mma_f16(acc[mt][nt], alf[mt], bf);
                }
            }
        }
        __syncthreads();
    }
    int r_base = wm * 64 + (lane >> 2);
    int c_base = n0 + wn * 32 + (lane & 3) * 2;
    float* Crow = g_Oslots + (size_t)slot0 * HIDDEN;
#pragma unroll
    for (int mt = 0; mt < 4; mt++) {
#pragma unroll
        for (int nt = 0; nt < 4; nt++) {
            int r = r_base + mt * 16;
            int c = c_base + nt * 8;
            *reinterpret_cast<float2*>(Crow + (size_t)r * HIDDEN + c) =
                make_float2(acc[mt][nt][0], acc[mt][nt][1]);
            *reinterpret_cast<float2*>(Crow + (size_t)(r + 8) * HIDDEN + c) =
                make_float2(acc[mt][nt][2], acc[mt][nt][3]);
        }
    }
}

__global__ void moe_combine_kernel(float* __restrict__ out) {
    int t = blockIdx.x;
    int c = threadIdx.x * 8;
    int s0 = g_token_slot[t * 2], s1 = g_token_slot[t * 2 + 1];
    float w0 = g_top_w[t * 2], w1 = g_top_w[t * 2 + 1];
    const float4* a = reinterpret_cast<const float4*>(g_Oslots + (size_t)s0 * HIDDEN + c);
    const float4* b = reinterpret_cast<const float4*>(g_Oslots + (size_t)s1 * HIDDEN + c);
    float4* o = reinterpret_cast<float4*>(out + (size_t)t * HIDDEN + c);
#pragma unroll
    for (int j = 0; j < 2; j++) {
        float4 av = a[j], bv = b[j];
        o[j] = make_float4(w0 * av.x + w1 * bv.x, w0 * av.y + w1 * bv.y,
                           w0 * av.z + w1 * bv.z, w0 * av.w + w1 * bv.w);
    }
}

// ---------------- launch ----------------
extern "C" void kernel_launch(void* const* d_in, const int* in_sizes, int n_in,
                              void* d_out, int out_size) {
    const float* x  = (const float*)d_in[0];
    const float* rw = (const float*)d_in[1];
    const float* wg = (const float*)d_in[2];
    const float* wu = (const float*)d_in[3];
    const float* wd = (const float*)d_in[4];
    float* out = (float*)d_out;

    cudaFuncSetAttribute(moe_gemm1, cudaFuncAttributeMaxDynamicSharedMemorySize, G1_SMEM);
    cudaFuncSetAttribute(moe_gemm2, cudaFuncAttributeMaxDynamicSharedMemorySize, G2_SMEM);

    dim3 tb(32, 8);
    moe_init_kernel<<<(MAX_SLOTS + 255) / 256, 256>>>();
    moe_transpose_kernel<<<dim3(INTER / 32, HIDDEN / 32, NEXP), tb>>>(wg, HIDDEN, INTER, 0);
    moe_transpose_kernel<<<dim3(INTER / 32, HIDDEN / 32, NEXP), tb>>>(wu, HIDDEN, INTER, 1);
    moe_transpose_kernel<<<dim3(HIDDEN / 32, INTER / 32, NEXP), tb>>>(wd, INTER, HIDDEN, 2);
    moe_router_kernel<<<TOKENS, 256>>>(x, rw);
    moe_schedule_kernel<<<1, 1>>>();
    moe_assign_kernel<<<(TOKENS + 255) / 256, 256>>>();
    moe_gather_kernel<<<MAX_SLOTS, 256>>>(x);
    moe_gemm1<<<dim3(MAX_MTILES, INTER / 64), 256, G1_SMEM>>>();
    moe_gemm2<<<dim3(MAX_MTILES, HIDDEN / 128), 256, G2_SMEM>>>();
    moe_combine_kernel<<<TOKENS, 256>>>(out);
}

// round 10
// speedup vs baseline: 3.8052x; 1.5901x over previous
#include <cuda_runtime.h>
#include <cuda_fp16.h>
#include <cstdint>
#include <cstddef>

#define HIDDEN 2048
#define INTER  1408
#define TOKENS 4096
#define NEXP   8
#define MAX_MTILES 72
#define MAX_SLOTS  (MAX_MTILES * 128)

// ---------------- device scratch ----------------
__device__ __align__(16) __half g_X[(size_t)MAX_SLOTS * HIDDEN];
__device__ __align__(16) __half g_Wg[(size_t)NEXP * INTER * HIDDEN]; // [e][i][h]
__device__ __align__(16) __half g_Wu[(size_t)NEXP * INTER * HIDDEN];
__device__ __align__(16) __half g_Wd[(size_t)NEXP * HIDDEN * INTER]; // [e][h][i]
__device__ __align__(16) __half g_H[(size_t)MAX_SLOTS * INTER];
__device__ __align__(16) float  g_Oslots[(size_t)MAX_SLOTS * HIDDEN];

__device__ int   g_top_idx[TOKENS * 2];
__device__ float g_top_w[TOKENS * 2];
__device__ int   g_counts[NEXP];
__device__ int   g_pos[NEXP];
__device__ int   g_expert_base[NEXP];
__device__ int   g_tile_expert[MAX_MTILES];
__device__ int   g_tile_slot0[MAX_MTILES];
__device__ int   g_perm_token[MAX_SLOTS];
__device__ int   g_token_slot[TOKENS * 2];

// ---------------- PTX helpers ----------------
__device__ __forceinline__ uint32_t smem_u32(const void* p) {
    uint32_t a;
    asm("{ .reg .u64 t; cvta.to.shared.u64 t, %1; cvt.u32.u64 %0, t; }" : "=r"(a) : "l"(p));
    return a;
}
#define CP_ASYNC16(sa, gp) asm volatile("cp.async.cg.shared.global [%0], [%1], 16;" :: "r"(sa), "l"(gp))
#define CP_COMMIT()        asm volatile("cp.async.commit_group;" ::: "memory")
#define CP_WAIT0()         asm volatile("cp.async.wait_group 0;" ::: "memory")
#define CP_WAIT1()         asm volatile("cp.async.wait_group 1;" ::: "memory")
#define CP_WAIT2()         asm volatile("cp.async.wait_group 2;" ::: "memory")

__device__ __forceinline__ void ldm_x4(uint32_t* r, uint32_t addr) {
    asm volatile("ldmatrix.sync.aligned.m8n8.x4.shared.b16 {%0,%1,%2,%3}, [%4];"
                 : "=r"(r[0]), "=r"(r[1]), "=r"(r[2]), "=r"(r[3]) : "r"(addr));
}
__device__ __forceinline__ void ldm_x2(uint32_t* r, uint32_t addr) {
    asm volatile("ldmatrix.sync.aligned.m8n8.x2.shared.b16 {%0,%1}, [%2];"
                 : "=r"(r[0]), "=r"(r[1]) : "r"(addr));
}
__device__ __forceinline__ void mma_f16(float* c, const uint32_t* a, const uint32_t* b) {
    asm volatile("mma.sync.aligned.m16n8k16.row.col.f32.f16.f16.f32 "
                 "{%0,%1,%2,%3}, {%4,%5,%6,%7}, {%8,%9}, {%0,%1,%2,%3};"
                 : "+f"(c[0]), "+f"(c[1]), "+f"(c[2]), "+f"(c[3])
                 : "r"(a[0]), "r"(a[1]), "r"(a[2]), "r"(a[3]), "r"(b[0]), "r"(b[1]));
}
__device__ __forceinline__ uint32_t sw128(uint32_t off) { return off ^ ((off >> 3) & 0x70); }

// ---------------- aux kernels ----------------
__global__ void moe_init_kernel() {
    int i = blockIdx.x * blockDim.x + threadIdx.x;
    if (i < NEXP) { g_counts[i] = 0; g_pos[i] = 0; }
    if (i < MAX_SLOTS) g_perm_token[i] = -1;
}

__global__ void moe_router_kernel(const float* __restrict__ x, const float* __restrict__ rw) {
    int t = blockIdx.x;
    float acc[NEXP];
#pragma unroll
    for (int e = 0; e < NEXP; e++) acc[e] = 0.f;
    for (int c = threadIdx.x; c < HIDDEN; c += 256) {
        float xv = x[(size_t)t * HIDDEN + c];
#pragma unroll
        for (int e = 0; e < NEXP; e++) acc[e] += xv * rw[e * HIDDEN + c];
    }
#pragma unroll
    for (int o = 16; o > 0; o >>= 1)
#pragma unroll
        for (int e = 0; e < NEXP; e++) acc[e] += __shfl_down_sync(0xFFFFFFFFu, acc[e], o);
    __shared__ float red[8][NEXP];
    int wid = threadIdx.x >> 5, lid = threadIdx.x & 31;
    if (lid == 0)
#pragma unroll
        for (int e = 0; e < NEXP; e++) red[wid][e] = acc[e];
    __syncthreads();
    if (threadIdx.x == 0) {
        float l[NEXP];
#pragma unroll
        for (int e = 0; e < NEXP; e++) {
            float s = 0.f;
            for (int w = 0; w < 8; w++) s += red[w][e];
            l[e] = s;
        }
        int i0 = 0;
        for (int e = 1; e < NEXP; e++) if (l[e] > l[i0]) i0 = e;
        int i1 = (i0 == 0) ? 1 : 0;
        for (int e = 0; e < NEXP; e++) if (e != i0 && l[e] > l[i1]) i1 = e;
        float e1 = __expf(l[i1] - l[i0]);
        float inv = 1.f / (1.f + e1);
        g_top_idx[t * 2 + 0] = i0;  g_top_w[t * 2 + 0] = inv;
        g_top_idx[t * 2 + 1] = i1;  g_top_w[t * 2 + 1] = e1 * inv;
        atomicAdd(&g_counts[i0], 1);
        atomicAdd(&g_counts[i1], 1);
    }
}

__global__ void moe_schedule_kernel() {
    int base = 0, mt = 0;
    for (int e = 0; e < NEXP; e++) {
        g_expert_base[e] = base;
        int nt = (g_counts[e] + 127) >> 7;
        for (int i = 0; i < nt && mt < MAX_MTILES; i++) {
            g_tile_expert[mt] = e;
            g_tile_slot0[mt] = base + i * 128;
            mt++;
        }
        base += nt * 128;
    }
    for (; mt < MAX_MTILES; mt++) g_tile_expert[mt] = -1;
}

__global__ void moe_assign_kernel() {
    int t = blockIdx.x * blockDim.x + threadIdx.x;
    if (t >= TOKENS) return;
#pragma unroll
    for (int k = 0; k < 2; k++) {
        int e = g_top_idx[t * 2 + k];
        int p = atomicAdd(&g_pos[e], 1);
        int s = g_expert_base[e] + p;
        g_perm_token[s] = t;
        g_token_slot[t * 2 + k] = s;
    }
}

union U8 { ushort u[8]; uint4 q; };

__global__ void moe_gather_kernel(const float* __restrict__ x) {
    int s = blockIdx.x;
    int t = g_perm_token[s];
    int c = threadIdx.x * 8;
    float v[8];
    if (t >= 0) {
        const float4* xp = reinterpret_cast<const float4*>(x + (size_t)t * HIDDEN + c);
        float4 a = xp[0], b = xp[1];
        v[0]=a.x; v[1]=a.y; v[2]=a.z; v[3]=a.w; v[4]=b.x; v[5]=b.y; v[6]=b.z; v[7]=b.w;
    } else {
#pragma unroll
        for (int i = 0; i < 8; i++) v[i] = 0.f;
    }
    U8 hi;
#pragma unroll
    for (int i = 0; i < 8; i++) hi.u[i] = __half_as_ushort(__float2half_rn(v[i]));
    *reinterpret_cast<uint4*>(g_X + (size_t)s * HIDDEN + c) = hi.q;
}

// Transpose [R,C] -> [C,R], fp16 out. block (32,8).
// which: 0 = gate+up merged (z = e + 8*sel), 2 = down (z = e)
__global__ void moe_transpose_gu_kernel(const float* __restrict__ wg, const float* __restrict__ wu) {
    __shared__ float tile[32][33];
    int z = blockIdx.z;
    int e = z & 7, sel = z >> 3;
    const int R = HIDDEN, C = INTER;
    const float* s = (sel ? wu : wg) + (size_t)e * R * C;
    __half* dh = (sel ? g_Wu : g_Wg) + (size_t)e * R * C;
    int c0 = blockIdx.x * 32, r0 = blockIdx.y * 32;
    int tx = threadIdx.x, ty = threadIdx.y;
#pragma unroll
    for (int j = 0; j < 4; j++)
        tile[ty + 8 * j][tx] = s[(size_t)(r0 + ty + 8 * j) * C + c0 + tx];
    __syncthreads();
#pragma unroll
    for (int j = 0; j < 4; j++) {
        float v = tile[tx][ty + 8 * j];
        int oc = c0 + ty + 8 * j, orr = r0 + tx;
        dh[(size_t)oc * R + orr] = __float2half_rn(v);
    }
}

__global__ void moe_transpose_d_kernel(const float* __restrict__ wd) {
    __shared__ float tile[32][33];
    int e = blockIdx.z;
    const int R = INTER, C = HIDDEN;
    const float* s = wd + (size_t)e * R * C;
    __half* dh = g_Wd + (size_t)e * R * C;
    int c0 = blockIdx.x * 32, r0 = blockIdx.y * 32;
    int tx = threadIdx.x, ty = threadIdx.y;
#pragma unroll
    for (int j = 0; j < 4; j++)
        tile[ty + 8 * j][tx] = s[(size_t)(r0 + ty + 8 * j) * C + c0 + tx];
    __syncthreads();
#pragma unroll
    for (int j = 0; j < 4; j++) {
        float v = tile[tx][ty + 8 * j];
        int oc = c0 + ty + 8 * j, orr = r0 + tx;
        dh[(size_t)oc * R + orr] = __float2half_rn(v);
    }
}

// ---------------- smem loaders ----------------
__device__ __forceinline__ void load_plane128(const __half* __restrict__ src, int ldk,
                                              uint32_t plane, int tid) {
#pragma unroll
    for (int it = 0; it < 4; it++) {
        int idx = tid + it * 256;
        int row = idx >> 3, v = idx & 7;
        CP_ASYNC16(plane + sw128((uint32_t)(row * 128 + v * 16)), src + (size_t)row * ldk + v * 8);
    }
}
__device__ __forceinline__ void load_plane64(const __half* __restrict__ src, int ldk,
                                             uint32_t plane, int tid) {
#pragma unroll
    for (int it = 0; it < 2; it++) {
        int idx = tid + it * 256;
        int row = idx >> 3, v = idx & 7;
        CP_ASYNC16(plane + sw128((uint32_t)(row * 128 + v * 16)), src + (size_t)row * ldk + v * 8);
    }
}

__device__ __forceinline__ float silu_mul(float g, float u) {
    return g / (1.f + __expf(-g)) * u;
}

// ---------------- GEMM1: fused gate+up+SiLU, single-pass fp16 ----------------
// stage: A 16K | Bg 8K | Bu 8K = 32KB; 3 stages = 96KB; 2 CTAs/SM
#define G1_STAGE 32768
#define G1_SMEM  (3 * G1_STAGE)
__global__ __launch_bounds__(256, 2) void moe_gemm1() {
    extern __shared__ char smem[];
    uint32_t sb = smem_u32(smem);
    int e = g_tile_expert[blockIdx.x];
    if (e < 0) return;
    int slot0 = g_tile_slot0[blockIdx.x];
    int n0 = blockIdx.y * 64;
    int tid = threadIdx.x, wid = tid >> 5, lane = tid & 31;
    int wm = wid & 1, wn = wid >> 1;   // warp tile: 64 rows x 16 cols (per matrix)

    const __half* A  = g_X + (size_t)slot0 * HIDDEN;
    const __half* Bg = g_Wg + ((size_t)e * INTER + n0) * HIDDEN;
    const __half* Bu = g_Wu + ((size_t)e * INTER + n0) * HIDDEN;

    float ag[4][2][4], au[4][2][4];
#pragma unroll
    for (int i = 0; i < 4; i++)
#pragma unroll
        for (int j = 0; j < 2; j++)
#pragma unroll
            for (int c = 0; c < 4; c++) { ag[i][j][c] = 0.f; au[i][j][c] = 0.f; }

    const int NK = HIDDEN / 64;
#pragma unroll
    for (int s = 0; s < 2; s++) {
        uint32_t st = sb + (uint32_t)s * G1_STAGE;
        int k0 = s * 64;
        load_plane128(A  + k0, HIDDEN, st,          tid);
        load_plane64 (Bg + k0, HIDDEN, st + 16384,  tid);
        load_plane64 (Bu + k0, HIDDEN, st + 24576,  tid);
        CP_COMMIT();
    }

    uint32_t a_off[4], b_off[2];
#pragma unroll
    for (int mt = 0; mt < 4; mt++) {
        int row = wm * 64 + mt * 16 + (lane & 15);
        a_off[mt] = sw128((uint32_t)(row * 128 + (lane >> 4) * 16));
    }
#pragma unroll
    for (int nt = 0; nt < 2; nt++) {
        int row = wn * 16 + nt * 8 + (lane & 7);
        b_off[nt] = sw128((uint32_t)(row * 128 + ((lane >> 3) & 1) * 16));
    }

    for (int kc = 0; kc < NK; kc++) {
        uint32_t cur = sb + (uint32_t)(kc % 3) * G1_STAGE;
        if (kc + 2 < NK) {
            uint32_t nxt = sb + (uint32_t)((kc + 2) % 3) * G1_STAGE;
            int k0 = (kc + 2) * 64;
            load_plane128(A  + k0, HIDDEN, nxt,          tid);
            load_plane64 (Bg + k0, HIDDEN, nxt + 16384,  tid);
            load_plane64 (Bu + k0, HIDDEN, nxt + 24576,  tid);
            CP_COMMIT();
            CP_WAIT2();
        } else if (kc + 1 < NK) {
            CP_WAIT1();
        } else {
            CP_WAIT0();
        }
        __syncthreads();
#pragma unroll
        for (int s = 0; s < 4; s++) {
            uint32_t ks = (uint32_t)(s * 32);
            uint32_t af[4][4];
#pragma unroll
            for (int mt = 0; mt < 4; mt++)
                ldm_x4(af[mt], cur + (a_off[mt] ^ ks));
#pragma unroll
            for (int nt = 0; nt < 2; nt++) {
                uint32_t bg[2], bu[2];
                ldm_x2(bg, cur + 16384 + (b_off[nt] ^ ks));
                ldm_x2(bu, cur + 24576 + (b_off[nt] ^ ks));
#pragma unroll
                for (int mt = 0; mt < 4; mt++) {
                    mma_f16(ag[mt][nt], af[mt], bg);
                    mma_f16(au[mt][nt], af[mt], bu);
                }
            }
        }
        __syncthreads();
    }
    // SiLU epilogue -> H (fp16)
    int r_base = wm * 64 + (lane >> 2);
    int c_base = n0 + wn * 16 + (lane & 3) * 2;
#pragma unroll
    for (int mt = 0; mt < 4; mt++) {
#pragma unroll
        for (int nt = 0; nt < 2; nt++) {
            int c = c_base + nt * 8;
#pragma unroll
            for (int half_ = 0; half_ < 2; half_++) {
                int r = r_base + mt * 16 + half_ * 8;
                float h0 = silu_mul(ag[mt][nt][half_ * 2],     au[mt][nt][half_ * 2]);
                float h1 = silu_mul(ag[mt][nt][half_ * 2 + 1], au[mt][nt][half_ * 2 + 1]);
                size_t off = (size_t)(slot0 + r) * INTER + c;
                *reinterpret_cast<__half2*>(g_H + off) =
                    __halves2half2(__float2half_rn(h0), __float2half_rn(h1));
            }
        }
    }
}

// ---------------- GEMM2: down, single-pass fp16 ----------------
// stage: A 16K | B 16K = 32KB; 3 stages = 96KB; 2 CTAs/SM
#define G2_STAGE 32768
#define G2_SMEM  (3 * G2_STAGE)
__global__ __launch_bounds__(256, 2) void moe_gemm2() {
    extern __shared__ char smem[];
    uint32_t sb = smem_u32(smem);
    int e = g_tile_expert[blockIdx.x];
    if (e < 0) return;
    int slot0 = g_tile_slot0[blockIdx.x];
    int n0 = blockIdx.y * 128;
    int tid = threadIdx.x, wid = tid >> 5, lane = tid & 31;
    int wm = wid & 1, wn = wid >> 1;   // warp tile 64 x 32

    const __half* A = g_H + (size_t)slot0 * INTER;
    const __half* B = g_Wd + ((size_t)e * HIDDEN + n0) * INTER;

    float acc[4][4][4];
#pragma unroll
    for (int i = 0; i < 4; i++)
#pragma unroll
        for (int j = 0; j < 4; j++)
#pragma unroll
            for (int c = 0; c < 4; c++) acc[i][j][c] = 0.f;

    const int NK = INTER / 64;
#pragma unroll
    for (int s = 0; s < 2; s++) {
        uint32_t st = sb + (uint32_t)s * G2_STAGE;
        int k0 = s * 64;
        load_plane128(A + k0, INTER, st,          tid);
        load_plane128(B + k0, INTER, st + 16384,  tid);
        CP_COMMIT();
    }

    uint32_t a_off[4], b_off[4];
#pragma unroll
    for (int mt = 0; mt < 4; mt++) {
        int row = wm * 64 + mt * 16 + (lane & 15);
        a_off[mt] = sw128((uint32_t)(row * 128 + (lane >> 4) * 16));
    }
#pragma unroll
    for (int nt = 0; nt < 4; nt++) {
        int row = wn * 32 + nt * 8 + (lane & 7);
        b_off[nt] = sw128((uint32_t)(row * 128 + ((lane >> 3) & 1) * 16));
    }

    for (int kc = 0; kc < NK; kc++) {
        uint32_t cur = sb + (uint32_t)(kc % 3) * G2_STAGE;
        if (kc + 2 < NK) {
            uint32_t nxt = sb + (uint32_t)((kc + 2) % 3) * G2_STAGE;
            int k0 = (kc + 2) * 64;
            load_plane128(A + k0, INTER, nxt,          tid);
            load_plane128(B + k0, INTER, nxt + 16384,  tid);
            CP_COMMIT();
            CP_WAIT2();
        } else if (kc + 1 < NK) {
            CP_WAIT1();
        } else {
            CP_WAIT0();
        }
        __syncthreads();
#pragma unroll
        for (int s = 0; s < 4; s++) {
            uint32_t ks = (uint32_t)(s * 32);
            uint32_t af[4][4];
#pragma unroll
            for (int mt = 0; mt < 4; mt++)
                ldm_x4(af[mt], cur + (a_off[mt] ^ ks));
#pragma unroll
            for (int nt = 0; nt < 4; nt++) {
                uint32_t bf[2];
                ldm_x2(bf, cur + 16384 + (b_off[nt] ^ ks));
#pragma unroll
                for (int mt = 0; mt < 4; mt++)
                    mma_f16(acc[mt][nt], af[mt], bf);
            }
        }
        __syncthreads();
    }
    int r_base = wm * 64 + (lane >> 2);
    int c_base = n0 + wn * 32 + (lane & 3) * 2;
    float* Crow = g_Oslots + (size_t)slot0 * HIDDEN;
#pragma unroll
    for (int mt = 0; mt < 4; mt++) {
#pragma unroll
        for (int nt = 0; nt < 4; nt++) {
            int r = r_base + mt * 16;
            int c = c_base + nt * 8;
            *reinterpret_cast<float2*>(Crow + (size_t)r * HIDDEN + c) =
                make_float2(acc[mt][nt][0], acc[mt][nt][1]);
            *reinterpret_cast<float2*>(Crow + (size_t)(r + 8) * HIDDEN + c) =
                make_float2(acc[mt][nt][2], acc[mt][nt][3]);
        }
    }
}

__global__ void moe_combine_kernel(float* __restrict__ out) {
    int t = blockIdx.x;
    int c = threadIdx.x * 8;
    int s0 = g_token_slot[t * 2], s1 = g_token_slot[t * 2 + 1];
    float w0 = g_top_w[t * 2], w1 = g_top_w[t * 2 + 1];
    const float4* a = reinterpret_cast<const float4*>(g_Oslots + (size_t)s0 * HIDDEN + c);
    const float4* b = reinterpret_cast<const float4*>(g_Oslots + (size_t)s1 * HIDDEN + c);
    float4* o = reinterpret_cast<float4*>(out + (size_t)t * HIDDEN + c);
#pragma unroll
    for (int j = 0; j < 2; j++) {
        float4 av = a[j], bv = b[j];
        o[j] = make_float4(w0 * av.x + w1 * bv.x, w0 * av.y + w1 * bv.y,
                           w0 * av.z + w1 * bv.z, w0 * av.w + w1 * bv.w);
    }
}

// ---------------- launch ----------------
extern "C" void kernel_launch(void* const* d_in, const int* in_sizes, int n_in,
                              void* d_out, int out_size) {
    const float* x  = (const float*)d_in[0];
    const float* rw = (const float*)d_in[1];
    const float* wg = (const float*)d_in[2];
    const float* wu = (const float*)d_in[3];
    const float* wd = (const float*)d_in[4];
    float* out = (float*)d_out;

    cudaFuncSetAttribute(moe_gemm1, cudaFuncAttributeMaxDynamicSharedMemorySize, G1_SMEM);
    cudaFuncSetAttribute(moe_gemm2, cudaFuncAttributeMaxDynamicSharedMemorySize, G2_SMEM);

    dim3 tb(32, 8);
    moe_init_kernel<<<(MAX_SLOTS + 255) / 256, 256>>>();
    moe_transpose_gu_kernel<<<dim3(INTER / 32, HIDDEN / 32, NEXP * 2), tb>>>(wg, wu);
    moe_transpose_d_kernel<<<dim3(HIDDEN / 32, INTER / 32, NEXP), tb>>>(wd);
    moe_router_kernel<<<TOKENS, 256>>>(x, rw);
    moe_schedule_kernel<<<1, 1>>>();
    moe_assign_kernel<<<(TOKENS + 255) / 256, 256>>>();
    moe_gather_kernel<<<MAX_SLOTS, 256>>>(x);
    moe_gemm1<<<dim3(MAX_MTILES, INTER / 64), 256, G1_SMEM>>>();
    moe_gemm2<<<dim3(MAX_MTILES, HIDDEN / 128), 256, G2_SMEM>>>();
    moe_combine_kernel<<<TOKENS, 256>>>(out);
}